// round 1
// baseline (speedup 1.0000x reference)
#include <cuda_runtime.h>

#define N_NODES 16384
#define DIM 128
#define NE 262144
#define NG 32
#define SEQ 512
#define NH 8
#define DHD 16
#define EPS 1e-5f
#define KPAD 514

// ---------------- scratch (device globals; no allocation allowed) ----------------
__device__ float g_z[N_NODES * DIM];
__device__ float g_t1[N_NODES * DIM];
__device__ float g_hl[N_NODES * DIM];
__device__ float g_qkv[N_NODES * 3 * DIM];
__device__ float g_o[N_NODES * DIM];
__device__ float g_ha[N_NODES * DIM];
__device__ float g_h[N_NODES * DIM];
__device__ float g_f1[N_NODES * 2 * DIM];
__device__ float g_sum[3 * DIM];
__device__ float g_sq[3 * DIM];

// ---------------- tiny utility kernels ----------------
__global__ void zero_stats_k() {
    int t = threadIdx.x;
    if (t < 3 * DIM) { g_sum[t] = 0.f; g_sq[t] = 0.f; }
}

__global__ void copy_k(const float* __restrict__ src, float* __restrict__ dst) {
    int i = blockIdx.x * blockDim.x + threadIdx.x;
    ((float4*)dst)[i] = ((const float4*)src)[i];
}

// ---------------- edge kernel: msg = relu(x[src]+edge_attr); atomic scatter to dst ----------------
__global__ void edge_k(const float* __restrict__ x, const int* __restrict__ ei,
                       const float* __restrict__ ea, float* __restrict__ z) {
    int t = blockIdx.x * blockDim.x + threadIdx.x;   // NE*32 threads
    int e = t >> 5;
    int c = t & 31;
    int s = __ldg(&ei[e]);
    int d = __ldg(&ei[NE + e]);
    float4 a = __ldg(&((const float4*)ea)[e * 32 + c]);
    float4 xv = __ldg(&((const float4*)x)[s * 32 + c]);
    float4 m;
    m.x = fmaxf(a.x + xv.x, 0.f);
    m.y = fmaxf(a.y + xv.y, 0.f);
    m.z = fmaxf(a.z + xv.z, 0.f);
    m.w = fmaxf(a.w + xv.w, 0.f);
    float* p = z + (size_t)d * DIM + c * 4;
    atomicAdd(p + 0, m.x);
    atomicAdd(p + 1, m.y);
    atomicAdd(p + 2, m.z);
    atomicAdd(p + 3, m.w);
}

// ---------------- generic GEMM: out[N,Dout] = f(A[N,K] @ W[Dout,K]^T + bias) (+res) ----------------
__global__ void __launch_bounds__(256) gemm_k(
    const float* __restrict__ A, const float* __restrict__ W,
    const float* __restrict__ bias, const float* __restrict__ res,
    float* __restrict__ out, int K, int Dout, int do_relu)
{
    __shared__ float As[16][68];
    __shared__ float Bs[16][68];
    int tid = threadIdx.x;
    int tx = tid & 15, ty = tid >> 4;
    int bm = blockIdx.x * 64, bn = blockIdx.y * 64;
    int lr = tid >> 2, lc = tid & 3;
    const float* Ap = A + (size_t)(bm + lr) * K + lc * 4;
    const float* Wp = W + (size_t)(bn + lr) * K + lc * 4;
    float acc[4][4];
#pragma unroll
    for (int i = 0; i < 4; i++)
#pragma unroll
        for (int j = 0; j < 4; j++) acc[i][j] = 0.f;

    for (int k0 = 0; k0 < K; k0 += 16) {
        float4 av = *(const float4*)(Ap + k0);
        float4 wv = *(const float4*)(Wp + k0);
        As[lc * 4 + 0][lr] = av.x; As[lc * 4 + 1][lr] = av.y;
        As[lc * 4 + 2][lr] = av.z; As[lc * 4 + 3][lr] = av.w;
        Bs[lc * 4 + 0][lr] = wv.x; Bs[lc * 4 + 1][lr] = wv.y;
        Bs[lc * 4 + 2][lr] = wv.z; Bs[lc * 4 + 3][lr] = wv.w;
        __syncthreads();
#pragma unroll
        for (int kk = 0; kk < 16; kk++) {
            float4 a = *(const float4*)&As[kk][ty << 2];
            float4 b = *(const float4*)&Bs[kk][tx << 2];
            acc[0][0] = fmaf(a.x, b.x, acc[0][0]); acc[0][1] = fmaf(a.x, b.y, acc[0][1]);
            acc[0][2] = fmaf(a.x, b.z, acc[0][2]); acc[0][3] = fmaf(a.x, b.w, acc[0][3]);
            acc[1][0] = fmaf(a.y, b.x, acc[1][0]); acc[1][1] = fmaf(a.y, b.y, acc[1][1]);
            acc[1][2] = fmaf(a.y, b.z, acc[1][2]); acc[1][3] = fmaf(a.y, b.w, acc[1][3]);
            acc[2][0] = fmaf(a.z, b.x, acc[2][0]); acc[2][1] = fmaf(a.z, b.y, acc[2][1]);
            acc[2][2] = fmaf(a.z, b.z, acc[2][2]); acc[2][3] = fmaf(a.z, b.w, acc[2][3]);
            acc[3][0] = fmaf(a.w, b.x, acc[3][0]); acc[3][1] = fmaf(a.w, b.y, acc[3][1]);
            acc[3][2] = fmaf(a.w, b.z, acc[3][2]); acc[3][3] = fmaf(a.w, b.w, acc[3][3]);
        }
        __syncthreads();
    }

    int colb = bn + (tx << 2);
    float4 bv = __ldg((const float4*)&bias[colb]);
#pragma unroll
    for (int i = 0; i < 4; i++) {
        int row = bm + (ty << 2) + i;
        float4 v;
        v.x = acc[i][0] + bv.x;
        v.y = acc[i][1] + bv.y;
        v.z = acc[i][2] + bv.z;
        v.w = acc[i][3] + bv.w;
        if (do_relu) {
            v.x = fmaxf(v.x, 0.f); v.y = fmaxf(v.y, 0.f);
            v.z = fmaxf(v.z, 0.f); v.w = fmaxf(v.w, 0.f);
        }
        if (res) {
            float4 r = __ldg((const float4*)&res[(size_t)row * Dout + colb]);
            v.x += r.x; v.y += r.y; v.z += r.z; v.w += r.w;
        }
        *(float4*)&out[(size_t)row * Dout + colb] = v;
    }
}

// ---------------- attention: one block per (graph, head) ----------------
__global__ void __launch_bounds__(256) attn_k(const float* __restrict__ qkv,
                                              float* __restrict__ o)
{
    extern __shared__ float sm[];
    float* Ks = sm;                  // [16][KPAD]
    float* Vs = sm + DHD * KPAD;     // [16][KPAD]
    int g = blockIdx.x >> 3, h = blockIdx.x & 7;
    int tid = threadIdx.x;
    const float* base = qkv + (size_t)g * SEQ * 384 + h * DHD;

    for (int idx = tid; idx < SEQ * DHD; idx += 256) {
        int key = idx >> 4, d = idx & 15;
        Ks[d * KPAD + key] = __ldg(&base[key * 384 + 128 + d]);
        Vs[d * KPAD + key] = __ldg(&base[key * 384 + 256 + d]);
    }
    __syncthreads();

    int warp = tid >> 5, lane = tid & 31;
    for (int q = warp; q < SEQ; q += 8) {
        const float* qp = base + q * 384;
        float qr[16];
#pragma unroll
        for (int d = 0; d < 16; d++) qr[d] = __ldg(&qp[d]);

        float sc[16];
#pragma unroll
        for (int c = 0; c < 16; c++) {
            int key = (c << 5) + lane;
            float s = 0.f;
#pragma unroll
            for (int d = 0; d < 16; d++) s = fmaf(qr[d], Ks[d * KPAD + key], s);
            sc[c] = s * 0.25f;   // 1/sqrt(16)
        }
        float m = sc[0];
#pragma unroll
        for (int c = 1; c < 16; c++) m = fmaxf(m, sc[c]);
#pragma unroll
        for (int off = 16; off; off >>= 1)
            m = fmaxf(m, __shfl_xor_sync(0xffffffffu, m, off));
        float ssum = 0.f;
#pragma unroll
        for (int c = 0; c < 16; c++) { sc[c] = __expf(sc[c] - m); ssum += sc[c]; }
#pragma unroll
        for (int off = 16; off; off >>= 1)
            ssum += __shfl_xor_sync(0xffffffffu, ssum, off);
        float inv = 1.0f / ssum;

        float acc[16];
#pragma unroll
        for (int d = 0; d < 16; d++) acc[d] = 0.f;
#pragma unroll
        for (int c = 0; c < 16; c++) {
            int key = (c << 5) + lane;
            float p = sc[c] * inv;
#pragma unroll
            for (int d = 0; d < 16; d++) acc[d] = fmaf(p, Vs[d * KPAD + key], acc[d]);
        }
        float ov = 0.f;
#pragma unroll
        for (int d = 0; d < 16; d++) {
            float t = acc[d];
#pragma unroll
            for (int off = 16; off; off >>= 1)
                t += __shfl_xor_sync(0xffffffffu, t, off);
            if (lane == d) ov = t;
        }
        if (lane < 16)
            o[(size_t)(g * SEQ + q) * DIM + h * DHD + lane] = ov;
    }
}

// ---------------- BN stats: per-column sum & sumsq (atomic partials) ----------------
__global__ void bn_stats_k(const float* __restrict__ hsrc, int slot) {
    int d = threadIdx.x;            // 128 threads = 128 columns
    int r0 = blockIdx.x * 128;      // 128 blocks x 128 rows
    float s = 0.f, qq = 0.f;
    for (int r = 0; r < 128; r++) {
        float v = hsrc[(size_t)(r0 + r) * DIM + d];
        s += v;
        qq += v * v;
    }
    atomicAdd(&g_sum[slot * DIM + d], s);
    atomicAdd(&g_sq[slot * DIM + d], qq);
}

// ---------------- combine: h = BN(h_local) + BN(h_attn) ----------------
__global__ void combine_k(const float* __restrict__ hl, const float* __restrict__ ha,
                          const float* __restrict__ g1, const float* __restrict__ b1,
                          const float* __restrict__ g2, const float* __restrict__ b2,
                          float* __restrict__ hout)
{
    int i = blockIdx.x * blockDim.x + threadIdx.x;
    int d = i & (DIM - 1);
    const float invN = 1.f / N_NODES;
    float mu1 = g_sum[d] * invN;
    float v1 = g_sq[d] * invN - mu1 * mu1;
    float mu2 = g_sum[DIM + d] * invN;
    float v2 = g_sq[DIM + d] * invN - mu2 * mu2;
    float a = (hl[i] - mu1) * rsqrtf(v1 + EPS) * __ldg(&g1[d]) + __ldg(&b1[d]);
    float b = (ha[i] - mu2) * rsqrtf(v2 + EPS) * __ldg(&g2[d]) + __ldg(&b2[d]);
    hout[i] = a + b;
}

// ---------------- final BN (in place on out) ----------------
__global__ void bn_apply_k(float* __restrict__ out,
                           const float* __restrict__ gamma, const float* __restrict__ beta)
{
    int i = blockIdx.x * blockDim.x + threadIdx.x;
    int d = i & (DIM - 1);
    const float invN = 1.f / N_NODES;
    float mu = g_sum[2 * DIM + d] * invN;
    float var = g_sq[2 * DIM + d] * invN - mu * mu;
    out[i] = (out[i] - mu) * rsqrtf(var + EPS) * __ldg(&gamma[d]) + __ldg(&beta[d]);
}

// ---------------- launch ----------------
extern "C" void kernel_launch(void* const* d_in, const int* in_sizes, int n_in,
                              void* d_out, int out_size)
{
    const float* x     = (const float*)d_in[0];
    const int*   ei    = (const int*)d_in[1];
    const float* ea    = (const float*)d_in[2];
    const float* gw1   = (const float*)d_in[3];
    const float* gb1   = (const float*)d_in[4];
    const float* gw2   = (const float*)d_in[5];
    const float* gb2   = (const float*)d_in[6];
    const float* bn1lg = (const float*)d_in[7];
    const float* bn1lb = (const float*)d_in[8];
    const float* aiw   = (const float*)d_in[9];
    const float* aib   = (const float*)d_in[10];
    const float* aow   = (const float*)d_in[11];
    const float* aob   = (const float*)d_in[12];
    const float* bn1ag = (const float*)d_in[13];
    const float* bn1ab = (const float*)d_in[14];
    const float* fw1   = (const float*)d_in[15];
    const float* fb1   = (const float*)d_in[16];
    const float* fw2   = (const float*)d_in[17];
    const float* fb2   = (const float*)d_in[18];
    const float* bn2g  = (const float*)d_in[19];
    const float* bn2b  = (const float*)d_in[20];
    float* out = (float*)d_out;

    float *p_z, *p_t1, *p_hl, *p_qkv, *p_o, *p_ha, *p_h, *p_f1;
    cudaGetSymbolAddress((void**)&p_z, g_z);
    cudaGetSymbolAddress((void**)&p_t1, g_t1);
    cudaGetSymbolAddress((void**)&p_hl, g_hl);
    cudaGetSymbolAddress((void**)&p_qkv, g_qkv);
    cudaGetSymbolAddress((void**)&p_o, g_o);
    cudaGetSymbolAddress((void**)&p_ha, g_ha);
    cudaGetSymbolAddress((void**)&p_h, g_h);
    cudaGetSymbolAddress((void**)&p_f1, g_f1);

    int attn_smem = 2 * DHD * KPAD * 4;  // 65792 B
    cudaFuncSetAttribute(attn_k, cudaFuncAttributeMaxDynamicSharedMemorySize, attn_smem);

    dim3 t256(256);

    // init
    zero_stats_k<<<1, 384>>>();
    copy_k<<<(N_NODES * DIM / 4) / 256, t256>>>(x, p_z);     // z = x

    // local branch: GINE
    edge_k<<<(NE * 32) / 256, t256>>>(x, ei, ea, p_z);       // z += scatter(relu(x[src]+ea))
    gemm_k<<<dim3(N_NODES / 64, 128 / 64), t256>>>(p_z, gw1, gb1, nullptr, p_t1, 128, 128, 1);
    gemm_k<<<dim3(N_NODES / 64, 128 / 64), t256>>>(p_t1, gw2, gb2, x, p_hl, 128, 128, 0);
    bn_stats_k<<<128, 128>>>(p_hl, 0);

    // global branch: MHA
    gemm_k<<<dim3(N_NODES / 64, 384 / 64), t256>>>(x, aiw, aib, nullptr, p_qkv, 128, 384, 0);
    attn_k<<<NG * NH, t256, attn_smem>>>(p_qkv, p_o);
    gemm_k<<<dim3(N_NODES / 64, 128 / 64), t256>>>(p_o, aow, aob, x, p_ha, 128, 128, 0);
    bn_stats_k<<<128, 128>>>(p_ha, 1);

    // combine + FFN
    combine_k<<<(N_NODES * DIM) / 256, t256>>>(p_hl, p_ha, bn1lg, bn1lb, bn1ag, bn1ab, p_h);
    gemm_k<<<dim3(N_NODES / 64, 256 / 64), t256>>>(p_h, fw1, fb1, nullptr, p_f1, 128, 256, 1);
    gemm_k<<<dim3(N_NODES / 64, 128 / 64), t256>>>(p_f1, fw2, fb2, p_h, out, 256, 128, 0);
    bn_stats_k<<<128, 128>>>(out, 2);
    bn_apply_k<<<(N_NODES * DIM) / 256, t256>>>(out, bn2g, bn2b);
}

// round 2
// speedup vs baseline: 1.3101x; 1.3101x over previous
#include <cuda_runtime.h>

#define N_NODES 16384
#define DIM 128
#define NE 262144
#define NG 32
#define SEQ 512
#define NH 8
#define DHD 16
#define EPS 1e-5f
#define KPAD 514
#define PADR 132

// ---------------- scratch (device globals; no allocation allowed) ----------------
__device__ float g_z[N_NODES * DIM];
__device__ float g_t1[N_NODES * DIM];
__device__ float g_hl[N_NODES * DIM];
__device__ float g_qkv[N_NODES * 3 * DIM];
__device__ float g_o[N_NODES * DIM];
__device__ float g_ha[N_NODES * DIM];
__device__ float g_h[N_NODES * DIM];
__device__ float g_f1[N_NODES * 2 * DIM];
__device__ float g_sum[3 * DIM];
__device__ float g_sq[3 * DIM];

// ---------------- tiny utility kernels ----------------
__global__ void zero_stats_k() {
    int t = threadIdx.x;
    if (t < 3 * DIM) { g_sum[t] = 0.f; g_sq[t] = 0.f; }
}

__global__ void copy_k(const float* __restrict__ src, float* __restrict__ dst) {
    int i = blockIdx.x * blockDim.x + threadIdx.x;
    ((float4*)dst)[i] = ((const float4*)src)[i];
}

// ---------------- edge kernel: msg = relu(x[src]+edge_attr); vector red to dst ----------------
__global__ void edge_k(const float* __restrict__ x, const int* __restrict__ ei,
                       const float* __restrict__ ea, float* __restrict__ z) {
    int t = blockIdx.x * blockDim.x + threadIdx.x;   // NE*32 threads
    int e = t >> 5;
    int c = t & 31;
    int s = __ldg(&ei[e]);
    int d = __ldg(&ei[NE + e]);
    float4 a = __ldg(&((const float4*)ea)[e * 32 + c]);
    float4 xv = __ldg(&((const float4*)x)[s * 32 + c]);
    float mx = fmaxf(a.x + xv.x, 0.f);
    float my = fmaxf(a.y + xv.y, 0.f);
    float mz = fmaxf(a.z + xv.z, 0.f);
    float mw = fmaxf(a.w + xv.w, 0.f);
    float* p = z + (size_t)d * DIM + c * 4;
    asm volatile("red.global.add.v4.f32 [%0], {%1,%2,%3,%4};"
                 :: "l"(p), "f"(mx), "f"(my), "f"(mz), "f"(mw) : "memory");
}

// ---------------- GEMM: out[N,Dout] = f(A[N,K] @ W[Dout,K]^T + bias) (+res) ----------------
// 128x128 block tile, 8x8 per-thread micro-tile (split 2x2 of 4x4), K-chunk 8.
#define FMA44(ACC, AV, BV)                                             \
    ACC[0][0] = fmaf(AV.x, BV.x, ACC[0][0]); ACC[0][1] = fmaf(AV.x, BV.y, ACC[0][1]); \
    ACC[0][2] = fmaf(AV.x, BV.z, ACC[0][2]); ACC[0][3] = fmaf(AV.x, BV.w, ACC[0][3]); \
    ACC[1][0] = fmaf(AV.y, BV.x, ACC[1][0]); ACC[1][1] = fmaf(AV.y, BV.y, ACC[1][1]); \
    ACC[1][2] = fmaf(AV.y, BV.z, ACC[1][2]); ACC[1][3] = fmaf(AV.y, BV.w, ACC[1][3]); \
    ACC[2][0] = fmaf(AV.z, BV.x, ACC[2][0]); ACC[2][1] = fmaf(AV.z, BV.y, ACC[2][1]); \
    ACC[2][2] = fmaf(AV.z, BV.z, ACC[2][2]); ACC[2][3] = fmaf(AV.z, BV.w, ACC[2][3]); \
    ACC[3][0] = fmaf(AV.w, BV.x, ACC[3][0]); ACC[3][1] = fmaf(AV.w, BV.y, ACC[3][1]); \
    ACC[3][2] = fmaf(AV.w, BV.z, ACC[3][2]); ACC[3][3] = fmaf(AV.w, BV.w, ACC[3][3]);

__global__ void __launch_bounds__(256) gemm_k(
    const float* __restrict__ A, const float* __restrict__ W,
    const float* __restrict__ bias, const float* __restrict__ res,
    float* __restrict__ out, int K, int Dout, int do_relu)
{
    __shared__ float As[8][PADR];
    __shared__ float Bs[8][PADR];
    int tid = threadIdx.x;
    int tx = tid & 15, ty = tid >> 4;
    int bm = blockIdx.x * 128, bn = blockIdx.y * 128;
    int lr = tid >> 1, lc = tid & 1;
    const float* Ap = A + (size_t)(bm + lr) * K + lc * 4;
    const float* Wp = W + (size_t)(bn + lr) * K + lc * 4;

    float acc[2][2][4][4];
#pragma unroll
    for (int a = 0; a < 2; a++)
#pragma unroll
        for (int b = 0; b < 2; b++)
#pragma unroll
            for (int i = 0; i < 4; i++)
#pragma unroll
                for (int j = 0; j < 4; j++) acc[a][b][i][j] = 0.f;

    for (int k0 = 0; k0 < K; k0 += 8) {
        float4 av = *(const float4*)(Ap + k0);
        float4 wv = *(const float4*)(Wp + k0);
        As[lc * 4 + 0][lr] = av.x; As[lc * 4 + 1][lr] = av.y;
        As[lc * 4 + 2][lr] = av.z; As[lc * 4 + 3][lr] = av.w;
        Bs[lc * 4 + 0][lr] = wv.x; Bs[lc * 4 + 1][lr] = wv.y;
        Bs[lc * 4 + 2][lr] = wv.z; Bs[lc * 4 + 3][lr] = wv.w;
        __syncthreads();
#pragma unroll
        for (int kk = 0; kk < 8; kk++) {
            float4 a0 = *(const float4*)&As[kk][ty * 4];
            float4 a1 = *(const float4*)&As[kk][64 + ty * 4];
            float4 b0 = *(const float4*)&Bs[kk][tx * 4];
            float4 b1 = *(const float4*)&Bs[kk][64 + tx * 4];
            FMA44(acc[0][0], a0, b0);
            FMA44(acc[0][1], a0, b1);
            FMA44(acc[1][0], a1, b0);
            FMA44(acc[1][1], a1, b1);
        }
        __syncthreads();
    }

#pragma unroll
    for (int ch = 0; ch < 2; ch++) {
        int c0 = bn + ch * 64 + tx * 4;
        float4 bv = __ldg((const float4*)&bias[c0]);
#pragma unroll
        for (int rh = 0; rh < 2; rh++) {
#pragma unroll
            for (int i = 0; i < 4; i++) {
                int row = bm + rh * 64 + ty * 4 + i;
                float4 v;
                v.x = acc[rh][ch][i][0] + bv.x;
                v.y = acc[rh][ch][i][1] + bv.y;
                v.z = acc[rh][ch][i][2] + bv.z;
                v.w = acc[rh][ch][i][3] + bv.w;
                if (do_relu) {
                    v.x = fmaxf(v.x, 0.f); v.y = fmaxf(v.y, 0.f);
                    v.z = fmaxf(v.z, 0.f); v.w = fmaxf(v.w, 0.f);
                }
                if (res) {
                    float4 r = __ldg((const float4*)&res[(size_t)row * Dout + c0]);
                    v.x += r.x; v.y += r.y; v.z += r.z; v.w += r.w;
                }
                *(float4*)&out[(size_t)row * Dout + c0] = v;
            }
        }
    }
}

// ---------------- attention: one block per (graph, head); 4 queries per warp-pass ----------------
__global__ void __launch_bounds__(256) attn_k(const float* __restrict__ qkv,
                                              float* __restrict__ o)
{
    extern __shared__ float sm[];
    float* Ks = sm;                  // [16][KPAD]
    float* Vs = sm + DHD * KPAD;     // [16][KPAD]
    int g = blockIdx.x >> 3, h = blockIdx.x & 7;
    int tid = threadIdx.x;
    const float* base = qkv + (size_t)g * SEQ * 384 + h * DHD;

    for (int idx = tid; idx < SEQ * DHD; idx += 256) {
        int key = idx >> 4, d = idx & 15;
        Ks[d * KPAD + key] = __ldg(&base[key * 384 + 128 + d]);
        Vs[d * KPAD + key] = __ldg(&base[key * 384 + 256 + d]);
    }
    __syncthreads();

    int warp = tid >> 5, lane = tid & 31;
    for (int qg = warp; qg < SEQ / 4; qg += 8) {
        int q0 = qg * 4;
        // load 4 queries (broadcast LDG.128)
        float4 qr[4][4];
#pragma unroll
        for (int qq = 0; qq < 4; qq++)
#pragma unroll
            for (int dd = 0; dd < 4; dd++)
                qr[qq][dd] = __ldg((const float4*)&base[(q0 + qq) * 384 + dd * 4]);

        // scores: each lane owns 16 keys (one per 32-key chunk)
        float sc[4][16];
#pragma unroll
        for (int c = 0; c < 16; c++) {
            int key = (c << 5) + lane;
            float s0 = 0.f, s1 = 0.f, s2 = 0.f, s3 = 0.f;
#pragma unroll
            for (int dd = 0; dd < 4; dd++) {
                float k0 = Ks[(dd * 4 + 0) * KPAD + key];
                float k1 = Ks[(dd * 4 + 1) * KPAD + key];
                float k2 = Ks[(dd * 4 + 2) * KPAD + key];
                float k3 = Ks[(dd * 4 + 3) * KPAD + key];
                s0 = fmaf(qr[0][dd].x, k0, s0); s0 = fmaf(qr[0][dd].y, k1, s0);
                s0 = fmaf(qr[0][dd].z, k2, s0); s0 = fmaf(qr[0][dd].w, k3, s0);
                s1 = fmaf(qr[1][dd].x, k0, s1); s1 = fmaf(qr[1][dd].y, k1, s1);
                s1 = fmaf(qr[1][dd].z, k2, s1); s1 = fmaf(qr[1][dd].w, k3, s1);
                s2 = fmaf(qr[2][dd].x, k0, s2); s2 = fmaf(qr[2][dd].y, k1, s2);
                s2 = fmaf(qr[2][dd].z, k2, s2); s2 = fmaf(qr[2][dd].w, k3, s2);
                s3 = fmaf(qr[3][dd].x, k0, s3); s3 = fmaf(qr[3][dd].y, k1, s3);
                s3 = fmaf(qr[3][dd].z, k2, s3); s3 = fmaf(qr[3][dd].w, k3, s3);
            }
            sc[0][c] = s0 * 0.25f; sc[1][c] = s1 * 0.25f;
            sc[2][c] = s2 * 0.25f; sc[3][c] = s3 * 0.25f;
        }

        // softmax per query
        float inv[4];
#pragma unroll
        for (int qq = 0; qq < 4; qq++) {
            float m = sc[qq][0];
#pragma unroll
            for (int c = 1; c < 16; c++) m = fmaxf(m, sc[qq][c]);
#pragma unroll
            for (int off = 16; off; off >>= 1)
                m = fmaxf(m, __shfl_xor_sync(0xffffffffu, m, off));
            float ssum = 0.f;
#pragma unroll
            for (int c = 0; c < 16; c++) { sc[qq][c] = __expf(sc[qq][c] - m); ssum += sc[qq][c]; }
#pragma unroll
            for (int off = 16; off; off >>= 1)
                ssum += __shfl_xor_sync(0xffffffffu, ssum, off);
            inv[qq] = 1.0f / ssum;
        }

        // P @ V
        float acc[4][16];
#pragma unroll
        for (int qq = 0; qq < 4; qq++)
#pragma unroll
            for (int dd = 0; dd < 16; dd++) acc[qq][dd] = 0.f;
#pragma unroll
        for (int c = 0; c < 16; c++) {
            int key = (c << 5) + lane;
            float p0 = sc[0][c] * inv[0];
            float p1 = sc[1][c] * inv[1];
            float p2 = sc[2][c] * inv[2];
            float p3 = sc[3][c] * inv[3];
#pragma unroll
            for (int dd = 0; dd < 16; dd++) {
                float v = Vs[dd * KPAD + key];
                acc[0][dd] = fmaf(p0, v, acc[0][dd]);
                acc[1][dd] = fmaf(p1, v, acc[1][dd]);
                acc[2][dd] = fmaf(p2, v, acc[2][dd]);
                acc[3][dd] = fmaf(p3, v, acc[3][dd]);
            }
        }

        // reduce across lanes; lane dd holds dim dd
#pragma unroll
        for (int qq = 0; qq < 4; qq++) {
            float ov = 0.f;
#pragma unroll
            for (int dd = 0; dd < 16; dd++) {
                float t = acc[qq][dd];
#pragma unroll
                for (int off = 16; off; off >>= 1)
                    t += __shfl_xor_sync(0xffffffffu, t, off);
                if (lane == dd) ov = t;
            }
            if (lane < 16)
                o[(size_t)(g * SEQ + q0 + qq) * DIM + h * DHD + lane] = ov;
        }
    }
}

// ---------------- BN stats: per-column sum & sumsq (atomic partials) ----------------
__global__ void bn_stats_k(const float* __restrict__ hsrc, int slot) {
    int d = threadIdx.x;
    int r0 = blockIdx.x * 128;
    float s = 0.f, qq = 0.f;
    for (int r = 0; r < 128; r++) {
        float v = hsrc[(size_t)(r0 + r) * DIM + d];
        s += v;
        qq += v * v;
    }
    atomicAdd(&g_sum[slot * DIM + d], s);
    atomicAdd(&g_sq[slot * DIM + d], qq);
}

// ---------------- combine: h = BN(h_local) + BN(h_attn) ----------------
__global__ void combine_k(const float* __restrict__ hl, const float* __restrict__ ha,
                          const float* __restrict__ g1, const float* __restrict__ b1,
                          const float* __restrict__ g2, const float* __restrict__ b2,
                          float* __restrict__ hout)
{
    int i = blockIdx.x * blockDim.x + threadIdx.x;
    int d = i & (DIM - 1);
    const float invN = 1.f / N_NODES;
    float mu1 = g_sum[d] * invN;
    float v1 = g_sq[d] * invN - mu1 * mu1;
    float mu2 = g_sum[DIM + d] * invN;
    float v2 = g_sq[DIM + d] * invN - mu2 * mu2;
    float a = (hl[i] - mu1) * rsqrtf(v1 + EPS) * __ldg(&g1[d]) + __ldg(&b1[d]);
    float b = (ha[i] - mu2) * rsqrtf(v2 + EPS) * __ldg(&g2[d]) + __ldg(&b2[d]);
    hout[i] = a + b;
}

// ---------------- final BN (in place on out) ----------------
__global__ void bn_apply_k(float* __restrict__ out,
                           const float* __restrict__ gamma, const float* __restrict__ beta)
{
    int i = blockIdx.x * blockDim.x + threadIdx.x;
    int d = i & (DIM - 1);
    const float invN = 1.f / N_NODES;
    float mu = g_sum[2 * DIM + d] * invN;
    float var = g_sq[2 * DIM + d] * invN - mu * mu;
    out[i] = (out[i] - mu) * rsqrtf(var + EPS) * __ldg(&gamma[d]) + __ldg(&beta[d]);
}

// ---------------- launch ----------------
extern "C" void kernel_launch(void* const* d_in, const int* in_sizes, int n_in,
                              void* d_out, int out_size)
{
    const float* x     = (const float*)d_in[0];
    const int*   ei    = (const int*)d_in[1];
    const float* ea    = (const float*)d_in[2];
    const float* gw1   = (const float*)d_in[3];
    const float* gb1   = (const float*)d_in[4];
    const float* gw2   = (const float*)d_in[5];
    const float* gb2   = (const float*)d_in[6];
    const float* bn1lg = (const float*)d_in[7];
    const float* bn1lb = (const float*)d_in[8];
    const float* aiw   = (const float*)d_in[9];
    const float* aib   = (const float*)d_in[10];
    const float* aow   = (const float*)d_in[11];
    const float* aob   = (const float*)d_in[12];
    const float* bn1ag = (const float*)d_in[13];
    const float* bn1ab = (const float*)d_in[14];
    const float* fw1   = (const float*)d_in[15];
    const float* fb1   = (const float*)d_in[16];
    const float* fw2   = (const float*)d_in[17];
    const float* fb2   = (const float*)d_in[18];
    const float* bn2g  = (const float*)d_in[19];
    const float* bn2b  = (const float*)d_in[20];
    float* out = (float*)d_out;

    float *p_z, *p_t1, *p_hl, *p_qkv, *p_o, *p_ha, *p_h, *p_f1;
    cudaGetSymbolAddress((void**)&p_z, g_z);
    cudaGetSymbolAddress((void**)&p_t1, g_t1);
    cudaGetSymbolAddress((void**)&p_hl, g_hl);
    cudaGetSymbolAddress((void**)&p_qkv, g_qkv);
    cudaGetSymbolAddress((void**)&p_o, g_o);
    cudaGetSymbolAddress((void**)&p_ha, g_ha);
    cudaGetSymbolAddress((void**)&p_h, g_h);
    cudaGetSymbolAddress((void**)&p_f1, g_f1);

    int attn_smem = 2 * DHD * KPAD * 4;  // 65792 B
    cudaFuncSetAttribute(attn_k, cudaFuncAttributeMaxDynamicSharedMemorySize, attn_smem);

    dim3 t256(256);

    // init
    zero_stats_k<<<1, 384>>>();
    copy_k<<<(N_NODES * DIM / 4) / 256, t256>>>(x, p_z);     // z = x

    // local branch: GINE
    edge_k<<<(NE * 32) / 256, t256>>>(x, ei, ea, p_z);       // z += scatter(relu(x[src]+ea))
    gemm_k<<<dim3(N_NODES / 128, 1), t256>>>(p_z, gw1, gb1, nullptr, p_t1, 128, 128, 1);
    gemm_k<<<dim3(N_NODES / 128, 1), t256>>>(p_t1, gw2, gb2, x, p_hl, 128, 128, 0);
    bn_stats_k<<<128, 128>>>(p_hl, 0);

    // global branch: MHA
    gemm_k<<<dim3(N_NODES / 128, 3), t256>>>(x, aiw, aib, nullptr, p_qkv, 128, 384, 0);
    attn_k<<<NG * NH, t256, attn_smem>>>(p_qkv, p_o);
    gemm_k<<<dim3(N_NODES / 128, 1), t256>>>(p_o, aow, aob, x, p_ha, 128, 128, 0);
    bn_stats_k<<<128, 128>>>(p_ha, 1);

    // combine + FFN
    combine_k<<<(N_NODES * DIM) / 256, t256>>>(p_hl, p_ha, bn1lg, bn1lb, bn1ag, bn1ab, p_h);
    gemm_k<<<dim3(N_NODES / 128, 2), t256>>>(p_h, fw1, fb1, nullptr, p_f1, 128, 256, 1);
    gemm_k<<<dim3(N_NODES / 128, 1), t256>>>(p_f1, fw2, fb2, p_h, out, 256, 128, 0);
    bn_stats_k<<<128, 128>>>(out, 2);
    bn_apply_k<<<(N_NODES * DIM) / 256, t256>>>(out, bn2g, bn2b);
}

// round 4
// speedup vs baseline: 1.6226x; 1.2385x over previous
#include <cuda_runtime.h>
#include <cstdint>

#define N_NODES 16384
#define DIM 128
#define NE 262144
#define NG 32
#define SEQ 512
#define NH 8
#define DHD 16
#define EPS 1e-5f
#define KPAD 514
#define APITCH 36

// ---------------- scratch ----------------
__device__ float g_z[N_NODES * DIM];
__device__ float g_t1[N_NODES * DIM];
__device__ float g_hl[N_NODES * DIM];
__device__ float g_qkv[N_NODES * 3 * DIM];
__device__ float g_o[N_NODES * DIM];
__device__ float g_ha[N_NODES * DIM];
__device__ float g_h[N_NODES * DIM];
__device__ float g_f1[N_NODES * 2 * DIM];
__device__ float g_sum[3 * DIM];
__device__ float g_sq[3 * DIM];

// ---------------- mma helpers ----------------
__device__ __forceinline__ uint32_t f2tf32(float f) {
    uint32_t u;
    asm("cvt.rna.tf32.f32 %0, %1;" : "=r"(u) : "f"(f));
    return u;
}

__device__ __forceinline__ void mma_tf32(float* d, const uint32_t* a, const uint32_t* b) {
    asm volatile(
        "mma.sync.aligned.m16n8k8.row.col.f32.tf32.tf32.f32 "
        "{%0,%1,%2,%3}, {%4,%5,%6,%7}, {%8,%9}, {%0,%1,%2,%3};"
        : "+f"(d[0]), "+f"(d[1]), "+f"(d[2]), "+f"(d[3])
        : "r"(a[0]), "r"(a[1]), "r"(a[2]), "r"(a[3]), "r"(b[0]), "r"(b[1]));
}

// ---------------- tf32 tensor-core GEMM ----------------
// out[N,Dout] = f(A[N,K] @ W[Dout,K]^T + bias) (+res)
// CTA: 128x128 tile, 128 threads = 4 warps in 2x2, each warp 64x64.
__global__ void __launch_bounds__(128) gemm_tc(
    const float* __restrict__ A, const float* __restrict__ W,
    const float* __restrict__ bias, const float* __restrict__ res,
    float* __restrict__ out, int K, int Dout, int do_relu)
{
    __shared__ uint32_t As[128 * APITCH];
    __shared__ uint32_t Bs[128 * APITCH];

    int tid = threadIdx.x;
    int wid = tid >> 5, lane = tid & 31;
    int wm = (wid & 1) * 64, wn = (wid >> 1) * 64;
    int bm = blockIdx.x * 128, bn = blockIdx.y * 128;
    int r = lane >> 2, c = lane & 3;

    float acc[4][8][4];
#pragma unroll
    for (int mi = 0; mi < 4; mi++)
#pragma unroll
        for (int ni = 0; ni < 8; ni++)
#pragma unroll
            for (int j = 0; j < 4; j++) acc[mi][ni][j] = 0.f;

    for (int kc = 0; kc < K; kc += 32) {
        // stage 128x32 chunks of A and W (tf32-converted), row-major pitch 36
#pragma unroll
        for (int it = 0; it < 8; it++) {
            int i = it * 128 + tid;          // 1024 float4 per matrix
            int row = i >> 3, q = i & 7;
            float4 av = __ldg((const float4*)&A[(size_t)(bm + row) * K + kc + q * 4]);
            float4 wv = __ldg((const float4*)&W[(size_t)(bn + row) * K + kc + q * 4]);
            uint32_t* pa = &As[row * APITCH + q * 4];
            uint32_t* pb = &Bs[row * APITCH + q * 4];
            pa[0] = f2tf32(av.x); pa[1] = f2tf32(av.y);
            pa[2] = f2tf32(av.z); pa[3] = f2tf32(av.w);
            pb[0] = f2tf32(wv.x); pb[1] = f2tf32(wv.y);
            pb[2] = f2tf32(wv.z); pb[3] = f2tf32(wv.w);
        }
        __syncthreads();

#pragma unroll
        for (int ks = 0; ks < 4; ks++) {
            int kb = ks * 8;
            uint32_t a[4][4], b[8][2];
#pragma unroll
            for (int mi = 0; mi < 4; mi++) {
                int row0 = wm + mi * 16 + r;
                a[mi][0] = As[row0 * APITCH + kb + c];
                a[mi][1] = As[(row0 + 8) * APITCH + kb + c];
                a[mi][2] = As[row0 * APITCH + kb + c + 4];
                a[mi][3] = As[(row0 + 8) * APITCH + kb + c + 4];
            }
#pragma unroll
            for (int ni = 0; ni < 8; ni++) {
                int nr = wn + ni * 8 + r;
                b[ni][0] = Bs[nr * APITCH + kb + c];
                b[ni][1] = Bs[nr * APITCH + kb + c + 4];
            }
#pragma unroll
            for (int mi = 0; mi < 4; mi++)
#pragma unroll
                for (int ni = 0; ni < 8; ni++)
                    mma_tf32(acc[mi][ni], a[mi], b[ni]);
        }
        __syncthreads();
    }

    // epilogue: c0,c1 at (row, col..col+1); c2,c3 at (row+8, col..col+1)
#pragma unroll
    for (int ni = 0; ni < 8; ni++) {
        int col = bn + wn + ni * 8 + c * 2;
        float2 bv = __ldg((const float2*)&bias[col]);
#pragma unroll
        for (int mi = 0; mi < 4; mi++) {
            int row0 = bm + wm + mi * 16 + r;
#pragma unroll
            for (int half = 0; half < 2; half++) {
                int row = row0 + half * 8;
                float2 v;
                v.x = acc[mi][ni][half * 2 + 0] + bv.x;
                v.y = acc[mi][ni][half * 2 + 1] + bv.y;
                if (do_relu) { v.x = fmaxf(v.x, 0.f); v.y = fmaxf(v.y, 0.f); }
                if (res) {
                    float2 rr = __ldg((const float2*)&res[(size_t)row * Dout + col]);
                    v.x += rr.x; v.y += rr.y;
                }
                *(float2*)&out[(size_t)row * Dout + col] = v;
            }
        }
    }
}

// ---------------- tiny utility kernels ----------------
__global__ void zero_stats_k() {
    int t = threadIdx.x;
    if (t < 3 * DIM) { g_sum[t] = 0.f; g_sq[t] = 0.f; }
}

__global__ void copy_k(const float* __restrict__ src, float* __restrict__ dst) {
    int i = blockIdx.x * blockDim.x + threadIdx.x;
    ((float4*)dst)[i] = ((const float4*)src)[i];
}

// ---------------- edge kernel ----------------
__global__ void edge_k(const float* __restrict__ x, const int* __restrict__ ei,
                       const float* __restrict__ ea, float* __restrict__ z) {
    int t = blockIdx.x * blockDim.x + threadIdx.x;
    int e = t >> 5;
    int c = t & 31;
    int s = __ldg(&ei[e]);
    int d = __ldg(&ei[NE + e]);
    float4 a = __ldg(&((const float4*)ea)[e * 32 + c]);
    float4 xv = __ldg(&((const float4*)x)[s * 32 + c]);
    float mx = fmaxf(a.x + xv.x, 0.f);
    float my = fmaxf(a.y + xv.y, 0.f);
    float mz = fmaxf(a.z + xv.z, 0.f);
    float mw = fmaxf(a.w + xv.w, 0.f);
    float* p = z + (size_t)d * DIM + c * 4;
    asm volatile("red.global.add.v4.f32 [%0], {%1,%2,%3,%4};"
                 :: "l"(p), "f"(mx), "f"(my), "f"(mz), "f"(mw) : "memory");
}

// ---------------- attention ----------------
__global__ void __launch_bounds__(256) attn_k(const float* __restrict__ qkv,
                                              float* __restrict__ o)
{
    extern __shared__ float sm[];
    float* Ks = sm;
    float* Vs = sm + DHD * KPAD;
    int g = blockIdx.x >> 3, h = blockIdx.x & 7;
    int tid = threadIdx.x;
    const float* base = qkv + (size_t)g * SEQ * 384 + h * DHD;

    for (int idx = tid; idx < SEQ * DHD; idx += 256) {
        int key = idx >> 4, d = idx & 15;
        Ks[d * KPAD + key] = __ldg(&base[key * 384 + 128 + d]);
        Vs[d * KPAD + key] = __ldg(&base[key * 384 + 256 + d]);
    }
    __syncthreads();

    int warp = tid >> 5, lane = tid & 31;
    for (int qg = warp; qg < SEQ / 4; qg += 8) {
        int q0 = qg * 4;
        float4 qr[4][4];
#pragma unroll
        for (int qq = 0; qq < 4; qq++)
#pragma unroll
            for (int dd = 0; dd < 4; dd++)
                qr[qq][dd] = __ldg((const float4*)&base[(q0 + qq) * 384 + dd * 4]);

        float sc[4][16];
#pragma unroll
        for (int c = 0; c < 16; c++) {
            int key = (c << 5) + lane;
            float s0 = 0.f, s1 = 0.f, s2 = 0.f, s3 = 0.f;
#pragma unroll
            for (int dd = 0; dd < 4; dd++) {
                float k0 = Ks[(dd * 4 + 0) * KPAD + key];
                float k1 = Ks[(dd * 4 + 1) * KPAD + key];
                float k2 = Ks[(dd * 4 + 2) * KPAD + key];
                float k3 = Ks[(dd * 4 + 3) * KPAD + key];
                s0 = fmaf(qr[0][dd].x, k0, s0); s0 = fmaf(qr[0][dd].y, k1, s0);
                s0 = fmaf(qr[0][dd].z, k2, s0); s0 = fmaf(qr[0][dd].w, k3, s0);
                s1 = fmaf(qr[1][dd].x, k0, s1); s1 = fmaf(qr[1][dd].y, k1, s1);
                s1 = fmaf(qr[1][dd].z, k2, s1); s1 = fmaf(qr[1][dd].w, k3, s1);
                s2 = fmaf(qr[2][dd].x, k0, s2); s2 = fmaf(qr[2][dd].y, k1, s2);
                s2 = fmaf(qr[2][dd].z, k2, s2); s2 = fmaf(qr[2][dd].w, k3, s2);
                s3 = fmaf(qr[3][dd].x, k0, s3); s3 = fmaf(qr[3][dd].y, k1, s3);
                s3 = fmaf(qr[3][dd].z, k2, s3); s3 = fmaf(qr[3][dd].w, k3, s3);
            }
            sc[0][c] = s0 * 0.25f; sc[1][c] = s1 * 0.25f;
            sc[2][c] = s2 * 0.25f; sc[3][c] = s3 * 0.25f;
        }

        float inv[4];
#pragma unroll
        for (int qq = 0; qq < 4; qq++) {
            float m = sc[qq][0];
#pragma unroll
            for (int c = 1; c < 16; c++) m = fmaxf(m, sc[qq][c]);
#pragma unroll
            for (int off = 16; off; off >>= 1)
                m = fmaxf(m, __shfl_xor_sync(0xffffffffu, m, off));
            float ssum = 0.f;
#pragma unroll
            for (int c = 0; c < 16; c++) { sc[qq][c] = __expf(sc[qq][c] - m); ssum += sc[qq][c]; }
#pragma unroll
            for (int off = 16; off; off >>= 1)
                ssum += __shfl_xor_sync(0xffffffffu, ssum, off);
            inv[qq] = 1.0f / ssum;
        }

        float acc[4][16];
#pragma unroll
        for (int qq = 0; qq < 4; qq++)
#pragma unroll
            for (int dd = 0; dd < 16; dd++) acc[qq][dd] = 0.f;
#pragma unroll
        for (int c = 0; c < 16; c++) {
            int key = (c << 5) + lane;
            float p0 = sc[0][c] * inv[0];
            float p1 = sc[1][c] * inv[1];
            float p2 = sc[2][c] * inv[2];
            float p3 = sc[3][c] * inv[3];
#pragma unroll
            for (int dd = 0; dd < 16; dd++) {
                float v = Vs[dd * KPAD + key];
                acc[0][dd] = fmaf(p0, v, acc[0][dd]);
                acc[1][dd] = fmaf(p1, v, acc[1][dd]);
                acc[2][dd] = fmaf(p2, v, acc[2][dd]);
                acc[3][dd] = fmaf(p3, v, acc[3][dd]);
            }
        }

#pragma unroll
        for (int qq = 0; qq < 4; qq++) {
            float ov = 0.f;
#pragma unroll
            for (int dd = 0; dd < 16; dd++) {
                float t = acc[qq][dd];
#pragma unroll
                for (int off = 16; off; off >>= 1)
                    t += __shfl_xor_sync(0xffffffffu, t, off);
                if (lane == dd) ov = t;
            }
            if (lane < 16)
                o[(size_t)(g * SEQ + q0 + qq) * DIM + h * DHD + lane] = ov;
        }
    }
}

// ---------------- BN stats ----------------
__global__ void bn_stats_k(const float* __restrict__ hsrc, int slot) {
    int d = threadIdx.x;
    int r0 = blockIdx.x * 128;
    float s = 0.f, qq = 0.f;
    for (int r = 0; r < 128; r++) {
        float v = hsrc[(size_t)(r0 + r) * DIM + d];
        s += v;
        qq += v * v;
    }
    atomicAdd(&g_sum[slot * DIM + d], s);
    atomicAdd(&g_sq[slot * DIM + d], qq);
}

// ---------------- combine ----------------
__global__ void combine_k(const float* __restrict__ hl, const float* __restrict__ ha,
                          const float* __restrict__ g1, const float* __restrict__ b1,
                          const float* __restrict__ g2, const float* __restrict__ b2,
                          float* __restrict__ hout)
{
    int i = blockIdx.x * blockDim.x + threadIdx.x;
    int d = i & (DIM - 1);
    const float invN = 1.f / N_NODES;
    float mu1 = g_sum[d] * invN;
    float v1 = g_sq[d] * invN - mu1 * mu1;
    float mu2 = g_sum[DIM + d] * invN;
    float v2 = g_sq[DIM + d] * invN - mu2 * mu2;
    float a = (hl[i] - mu1) * rsqrtf(v1 + EPS) * __ldg(&g1[d]) + __ldg(&b1[d]);
    float b = (ha[i] - mu2) * rsqrtf(v2 + EPS) * __ldg(&g2[d]) + __ldg(&b2[d]);
    hout[i] = a + b;
}

// ---------------- final BN ----------------
__global__ void bn_apply_k(float* __restrict__ out,
                           const float* __restrict__ gamma, const float* __restrict__ beta)
{
    int i = blockIdx.x * blockDim.x + threadIdx.x;
    int d = i & (DIM - 1);
    const float invN = 1.f / N_NODES;
    float mu = g_sum[2 * DIM + d] * invN;
    float var = g_sq[2 * DIM + d] * invN - mu * mu;
    out[i] = (out[i] - mu) * rsqrtf(var + EPS) * __ldg(&gamma[d]) + __ldg(&beta[d]);
}

// ---------------- launch ----------------
extern "C" void kernel_launch(void* const* d_in, const int* in_sizes, int n_in,
                              void* d_out, int out_size)
{
    const float* x     = (const float*)d_in[0];
    const int*   ei    = (const int*)d_in[1];
    const float* ea    = (const float*)d_in[2];
    const float* gw1   = (const float*)d_in[3];
    const float* gb1   = (const float*)d_in[4];
    const float* gw2   = (const float*)d_in[5];
    const float* gb2   = (const float*)d_in[6];
    const float* bn1lg = (const float*)d_in[7];
    const float* bn1lb = (const float*)d_in[8];
    const float* aiw   = (const float*)d_in[9];
    const float* aib   = (const float*)d_in[10];
    const float* aow   = (const float*)d_in[11];
    const float* aob   = (const float*)d_in[12];
    const float* bn1ag = (const float*)d_in[13];
    const float* bn1ab = (const float*)d_in[14];
    const float* fw1   = (const float*)d_in[15];
    const float* fb1   = (const float*)d_in[16];
    const float* fw2   = (const float*)d_in[17];
    const float* fb2   = (const float*)d_in[18];
    const float* bn2g  = (const float*)d_in[19];
    const float* bn2b  = (const float*)d_in[20];
    float* out = (float*)d_out;

    float *p_z, *p_t1, *p_hl, *p_qkv, *p_o, *p_ha, *p_h, *p_f1;
    cudaGetSymbolAddress((void**)&p_z, g_z);
    cudaGetSymbolAddress((void**)&p_t1, g_t1);
    cudaGetSymbolAddress((void**)&p_hl, g_hl);
    cudaGetSymbolAddress((void**)&p_qkv, g_qkv);
    cudaGetSymbolAddress((void**)&p_o, g_o);
    cudaGetSymbolAddress((void**)&p_ha, g_ha);
    cudaGetSymbolAddress((void**)&p_h, g_h);
    cudaGetSymbolAddress((void**)&p_f1, g_f1);

    int attn_smem = 2 * DHD * KPAD * 4;
    cudaFuncSetAttribute(attn_k, cudaFuncAttributeMaxDynamicSharedMemorySize, attn_smem);

    dim3 t256(256);
    dim3 t128(128);
    const int MB = N_NODES / 128;

    // init
    zero_stats_k<<<1, 384>>>();
    copy_k<<<(N_NODES * DIM / 4) / 256, t256>>>(x, p_z);

    // local branch: GINE
    edge_k<<<(NE * 32) / 256, t256>>>(x, ei, ea, p_z);
    gemm_tc<<<dim3(MB, 1), t128>>>(p_z, gw1, gb1, nullptr, p_t1, 128, 128, 1);
    gemm_tc<<<dim3(MB, 1), t128>>>(p_t1, gw2, gb2, x, p_hl, 128, 128, 0);
    bn_stats_k<<<128, 128>>>(p_hl, 0);

    // global branch: MHA
    gemm_tc<<<dim3(MB, 3), t128>>>(x, aiw, aib, nullptr, p_qkv, 128, 384, 0);
    attn_k<<<NG * NH, t256, attn_smem>>>(p_qkv, p_o);
    gemm_tc<<<dim3(MB, 1), t128>>>(p_o, aow, aob, x, p_ha, 128, 128, 0);
    bn_stats_k<<<128, 128>>>(p_ha, 1);

    // combine + FFN
    combine_k<<<(N_NODES * DIM) / 256, t256>>>(p_hl, p_ha, bn1lg, bn1lb, bn1ag, bn1ab, p_h);
    gemm_tc<<<dim3(MB, 2), t128>>>(p_h, fw1, fb1, nullptr, p_f1, 128, 256, 1);
    gemm_tc<<<dim3(MB, 1), t128>>>(p_f1, fw2, fb2, p_h, out, 256, 128, 0);
    bn_stats_k<<<128, 128>>>(out, 2);
    bn_apply_k<<<(N_NODES * DIM) / 256, t256>>>(out, bn2g, bn2b);
}